// round 14
// baseline (speedup 1.0000x reference)
#include <cuda_runtime.h>
#include <math.h>

#define NUM_B 8192
#define T_LEN 1024
#define HID   64
#define EPSF  1e-6f
#define SEGS  32
#define SLEN  (T_LEN / SEGS)
#define OPITCH 36
#define BWARPS 8
#define SHP   68          // sh row pitch in floats: 272B = 17*16 -> float4-aligned rows

// ---------------------------------------------------------------------------
// Fused kernel: per-block (8 rows) MLP -> odds constants -> warp-per-row scan.
// MLP mapping: warp w owns cols [8w, 8w+8); lane = (row = lane>>2, colpair =
// lane&3). Weight traffic = 32 KB/block (minimum), via __ldg (L1-resident).
// ---------------------------------------------------------------------------
__global__ __launch_bounds__(256) void fused_kernel(
    const int*   __restrict__ X,
    const int*   __restrict__ y,
    const float* __restrict__ embed,
    const float* __restrict__ W0, const float* __restrict__ b0,
    const float* __restrict__ W1, const float* __restrict__ b1,
    const float* __restrict__ Wout, const float* __restrict__ bout,
    float*       __restrict__ out)
{
    __shared__ __align__(16) float s_o[BWARPS][SEGS * OPITCH];  // 36.9 KB
    __shared__ __align__(16) float sh[2][BWARPS][SHP];
    __shared__ float sp[BWARPS][4];
    __shared__ float cA0[BWARPS], cA1[BWARPS], cB[BWARPS],
                     cO0[BWARPS], cS1[BWARPS], cGG[BWARPS];
    __shared__ int   sX[BWARPS];

    const int t    = threadIdx.x;
    const int w    = t >> 5;
    const int lane = t & 31;
    const int rowbase = blockIdx.x * BWARPS;
    const int row  = rowbase + w;

    if (t < BWARPS) sX[t] = X[rowbase + t];

    // ---- mask build (independent; overlaps everything) ----
    const int* yrow = y + (size_t)row * T_LEN;
    unsigned mask = 0;
    {
        int v[16];
#pragma unroll
        for (int c = 0; c < 16; ++c) v[c] = yrow[c * SLEN + lane];
#pragma unroll
        for (int c = 0; c < 16; ++c) {
            const unsigned m = __ballot_sync(0xffffffffu, v[c] > 0);
            if (lane == c) mask = m;
        }
#pragma unroll
        for (int c = 0; c < 16; ++c) v[c] = yrow[(16 + c) * SLEN + lane];
#pragma unroll
        for (int c = 0; c < 16; ++c) {
            const unsigned m = __ballot_sync(0xffffffffu, v[c] > 0);
            if (lane == 16 + c) mask = m;
        }
    }
    __syncthreads();   // sX visible

    // ---- embed gather: 128 threads, 8 rows x 16 float4 ----
    if (t < 128) {
        const int r  = t >> 4;
        const int i4 = (t & 15) * 4;
        const float4 e = *reinterpret_cast<const float4*>(
            &embed[(size_t)sX[r] * HID + i4]);
        *reinterpret_cast<float4*>(&sh[0][r][i4]) = e;
    }
    __syncthreads();

    // ---- layer 0: warp w -> cols [8w, 8w+8); lane -> (row, colpair) ----
    const int rr = lane >> 2;
    const int cp = (w << 3) + ((lane & 3) << 1);
    {
        float a0 = __ldg(&b0[cp]), a1 = __ldg(&b0[cp + 1]);
#pragma unroll
        for (int i = 0; i < HID; ++i) {
            const float hb = sh[0][rr][i];
            const float2 wv = __ldg(reinterpret_cast<const float2*>(&W0[i * HID + cp]));
            a0 = fmaf(hb, wv.x, a0);
            a1 = fmaf(hb, wv.y, a1);
        }
        sh[1][rr][cp]     = fmaxf(a0, 0.0f);
        sh[1][rr][cp + 1] = fmaxf(a1, 0.0f);
    }
    __syncthreads();

    // ---- layer 1 ----
    {
        float a0 = __ldg(&b1[cp]), a1 = __ldg(&b1[cp + 1]);
#pragma unroll
        for (int i = 0; i < HID; ++i) {
            const float hb = sh[1][rr][i];
            const float2 wv = __ldg(reinterpret_cast<const float2*>(&W1[i * HID + cp]));
            a0 = fmaf(hb, wv.x, a0);
            a1 = fmaf(hb, wv.y, a1);
        }
        sh[0][rr][cp]     = fmaxf(a0, 0.0f);
        sh[0][rr][cp + 1] = fmaxf(a1, 0.0f);
    }
    __syncthreads();

    // ---- head + sigmoid: 32 threads = 8 rows x 4 units ----
    if (t < 32) {
        const int hr = t >> 2;
        const int jo = t & 3;
        float a2 = __ldg(&bout[jo]);
#pragma unroll
        for (int i = 0; i < HID; ++i)
            a2 = fmaf(sh[0][hr][i], __ldg(&Wout[i * 4 + jo]), a2);
        float pv = 1.0f / (1.0f + expf(-a2));
        sp[hr][jo] = fminf(fmaxf(pv, EPSF), 1.0f - EPSF);
    }
    __syncthreads();

    // ---- odds-space constants per row ----
    if (t < BWARPS) {
        const float l  = sp[t][0];
        const float gg = sp[t][1];
        const float s  = sp[t][2];
        const float pr = sp[t][3];
        const float il = 1.0f / (1.0f - l);
        cA1[t] = (1.0f - s) / (gg * (1.0f - l));
        cA0[t] = s / ((1.0f - gg) * (1.0f - l));
        cB[t]  = l * il;
        cO0[t] = pr / (1.0f - pr);
        cS1[t] = 1.0f - s;
        cGG[t] = gg;
    }
    __syncthreads();

    // =================== scan phase (R10 body) ===================
    const float A0 = cA0[w];
    const float A1 = cA1[w];
    const float Bc = cB[w];
    const float s1 = cS1[w];
    const float gg = cGG[w];
    const float o0 = cO0[w];
    const float OMAX = (1.0f - EPSF) / EPSF;

    // compose segment map f(o) = min(a*o + b, c)
    float a = 1.0f, b = 0.0f, cc = OMAX;
#pragma unroll
    for (int j = 0; j < SLEN; ++j) {
        const float A = ((mask >> j) & 1u) ? A1 : A0;
        cc = fminf(fmaf(A, cc, Bc), OMAX);
        b  = fmaf(A, b, Bc);
        a  = A * a;
    }

    // inclusive Kogge-Stone scan over maps
#pragma unroll
    for (int d = 1; d < 32; d <<= 1) {
        const float ap = __shfl_up_sync(0xffffffffu, a,  d);
        const float bp = __shfl_up_sync(0xffffffffu, b,  d);
        const float cq = __shfl_up_sync(0xffffffffu, cc, d);
        if (lane >= d) {
            const float bn = fmaf(a, bp, b);
            const float cn = fminf(fmaf(a, cq, b), cc);
            a  = a * ap;
            b  = bn;
            cc = cn;
        }
    }
    const float ap = __shfl_up_sync(0xffffffffu, a,  1);
    const float bp = __shfl_up_sync(0xffffffffu, b,  1);
    const float cq = __shfl_up_sync(0xffffffffu, cc, 1);
    float o = (lane == 0) ? o0 : fminf(fmaf(ap, o0, bp), cq);

    // emit: batch 4 steps into float4, STS.128
    float* const so = &s_o[w][lane * OPITCH];
#pragma unroll
    for (int j4 = 0; j4 < SLEN / 4; ++j4) {
        float4 ov;
        {   const float A = ((mask >> (4*j4+0)) & 1u) ? A1 : A0;
            ov.x = o;  o = fminf(fmaf(A, o, Bc), OMAX); }
        {   const float A = ((mask >> (4*j4+1)) & 1u) ? A1 : A0;
            ov.y = o;  o = fminf(fmaf(A, o, Bc), OMAX); }
        {   const float A = ((mask >> (4*j4+2)) & 1u) ? A1 : A0;
            ov.z = o;  o = fminf(fmaf(A, o, Bc), OMAX); }
        {   const float A = ((mask >> (4*j4+3)) & 1u) ? A1 : A0;
            ov.w = o;  o = fminf(fmaf(A, o, Bc), OMAX); }
        *reinterpret_cast<float4*>(so + 4 * j4) = ov;
    }
    __syncwarp();

    // drain: LDS.128 + rcp x4 + 2x STG.128 per group
    float* const outc = out + (size_t)row * T_LEN;
    float* const outl = out + (size_t)NUM_B * T_LEN + (size_t)row * T_LEN;
    const int sgl = lane >> 3;
    const int k4  = (lane & 7) * 4;
#pragma unroll
    for (int dd = 0; dd < 8; ++dd) {
        const int seg = dd * 4 + sgl;
        const float4 ov = *reinterpret_cast<const float4*>(&s_o[w][seg * OPITCH + k4]);
        float4 lv, cv;
        float inv;
        asm("rcp.approx.ftz.f32 %0, %1;" : "=f"(inv) : "f"(1.0f + ov.x));
        lv.x = ov.x * inv;  cv.x = fmaf(ov.x, s1, gg) * inv;
        asm("rcp.approx.ftz.f32 %0, %1;" : "=f"(inv) : "f"(1.0f + ov.y));
        lv.y = ov.y * inv;  cv.y = fmaf(ov.y, s1, gg) * inv;
        asm("rcp.approx.ftz.f32 %0, %1;" : "=f"(inv) : "f"(1.0f + ov.z));
        lv.z = ov.z * inv;  cv.z = fmaf(ov.z, s1, gg) * inv;
        asm("rcp.approx.ftz.f32 %0, %1;" : "=f"(inv) : "f"(1.0f + ov.w));
        lv.w = ov.w * inv;  cv.w = fmaf(ov.w, s1, gg) * inv;
        *reinterpret_cast<float4*>(outc + seg * SLEN + k4) = cv;
        *reinterpret_cast<float4*>(outl + seg * SLEN + k4) = lv;
    }
}

// ---------------------------------------------------------------------------
extern "C" void kernel_launch(void* const* d_in, const int* in_sizes, int n_in,
                              void* d_out, int out_size)
{
    const int*   X     = (const int*)  d_in[0];
    const int*   y     = (const int*)  d_in[1];
    const float* embed = (const float*)d_in[2];
    const float* W0    = (const float*)d_in[3];
    const float* b0    = (const float*)d_in[4];
    const float* W1    = (const float*)d_in[5];
    const float* b1    = (const float*)d_in[6];
    const float* Wout  = (const float*)d_in[7];
    const float* bout  = (const float*)d_in[8];

    fused_kernel<<<NUM_B / BWARPS, 32 * BWARPS>>>(
        X, y, embed, W0, b0, W1, b1, Wout, bout, (float*)d_out);
}

// round 15
// speedup vs baseline: 1.2280x; 1.2280x over previous
#include <cuda_runtime.h>
#include <math.h>

#define NUM_B 8192
#define T_LEN 1024
#define HID   64
#define EPSF  1e-6f
#define SEGS  32
#define SLEN  (T_LEN / SEGS)
#define OPITCH 36
#define BWARPS 8
#define HPITCH 68
#define MROWS 64
#define NMLP  (NUM_B / MROWS)     // 128 producer blocks

// Per-row scan constants + publication flags (zero-init at module load; monotone).
__device__ float g_A0[NUM_B], g_A1[NUM_B], g_B[NUM_B],
                 g_o0[NUM_B], g_s1[NUM_B], g_gg[NUM_B];
__device__ int   g_flag[NMLP];

#define SBUF_BYTES 36928   // >= max(scan 36864, mlp 16384+17408)

__global__ __launch_bounds__(256) void fused_kernel(
    const int*   __restrict__ X,
    const int*   __restrict__ y,
    const float* __restrict__ embed,
    const float* __restrict__ W0, const float* __restrict__ b0,
    const float* __restrict__ W1, const float* __restrict__ b1,
    const float* __restrict__ Wout, const float* __restrict__ bout,
    float*       __restrict__ out)
{
    __shared__ __align__(16) char sbuf[SBUF_BYTES];   // union: mlp sW+sh / scan s_o
    __shared__ float sWo[HID * 4];
    __shared__ float sb0[HID], sb1[HID], sbo[4];
    __shared__ float sp[MROWS][4];

    const int t    = threadIdx.x;
    const int w    = t >> 5;
    const int lane = t & 31;
    const int bid  = blockIdx.x;
    const int row  = bid * BWARPS + w;      // this block's scan rows

    // ---- mask build (all blocks; y DRAM loads overlap producer MLP) ----
    const int* yrow = y + (size_t)row * T_LEN;
    unsigned mask = 0;
    {
        int v[16];
#pragma unroll
        for (int c = 0; c < 16; ++c) v[c] = yrow[c * SLEN + lane];
#pragma unroll
        for (int c = 0; c < 16; ++c) {
            const unsigned m = __ballot_sync(0xffffffffu, v[c] > 0);
            if (lane == c) mask = m;
        }
#pragma unroll
        for (int c = 0; c < 16; ++c) v[c] = yrow[(16 + c) * SLEN + lane];
#pragma unroll
        for (int c = 0; c < 16; ++c) {
            const unsigned m = __ballot_sync(0xffffffffu, v[c] > 0);
            if (lane == 16 + c) mask = m;
        }
    }

    // ================= producer role: blocks 0..127 run the R10 MLP =========
    if (bid < NMLP) {
        float* const sW = reinterpret_cast<float*>(sbuf);                 // 16 KB
        float (*sh)[HPITCH] = reinterpret_cast<float (*)[HPITCH]>(sbuf + 16384);

        const int c4 = (t & 7) * 4;
        const int rp = (t >> 3) * 2;
        const int growbase = bid * MROWS;

#pragma unroll
        for (int i = t; i < HID * HID / 4; i += 256)
            reinterpret_cast<float4*>(sW)[i] = reinterpret_cast<const float4*>(W0)[i];
        if (t < HID) { sb0[t] = b0[t]; sb1[t] = b1[t]; }
        if (t < HID) reinterpret_cast<float4*>(sWo)[t] = reinterpret_cast<const float4*>(Wout)[t];
        if (t < 4)   sbo[t] = bout[t];

#pragma unroll
        for (int rr = 0; rr < 2; ++rr) {
            const int xi = X[growbase + rp + rr];
            const float4 e0 = *reinterpret_cast<const float4*>(&embed[(size_t)xi * HID + c4]);
            const float4 e1 = *reinterpret_cast<const float4*>(&embed[(size_t)xi * HID + c4 + 32]);
            *reinterpret_cast<float4*>(&sh[rp + rr][c4])      = e0;
            *reinterpret_cast<float4*>(&sh[rp + rr][c4 + 32]) = e1;
        }
        __syncthreads();

        float acc[16];
        // layer 0
#pragma unroll
        for (int rr = 0; rr < 2; ++rr)
#pragma unroll
            for (int k = 0; k < 4; ++k) {
                acc[rr * 8 + k]     = sb0[c4 + k];
                acc[rr * 8 + 4 + k] = sb0[c4 + 32 + k];
            }
#pragma unroll
        for (int i = 0; i < HID; ++i) {
            const float4 w0 = *reinterpret_cast<const float4*>(&sW[i * HID + c4]);
            const float4 w1 = *reinterpret_cast<const float4*>(&sW[i * HID + c4 + 32]);
#pragma unroll
            for (int rr = 0; rr < 2; ++rr) {
                const float hb = sh[rp + rr][i];
                acc[rr*8+0] = fmaf(hb, w0.x, acc[rr*8+0]);
                acc[rr*8+1] = fmaf(hb, w0.y, acc[rr*8+1]);
                acc[rr*8+2] = fmaf(hb, w0.z, acc[rr*8+2]);
                acc[rr*8+3] = fmaf(hb, w0.w, acc[rr*8+3]);
                acc[rr*8+4] = fmaf(hb, w1.x, acc[rr*8+4]);
                acc[rr*8+5] = fmaf(hb, w1.y, acc[rr*8+5]);
                acc[rr*8+6] = fmaf(hb, w1.z, acc[rr*8+6]);
                acc[rr*8+7] = fmaf(hb, w1.w, acc[rr*8+7]);
            }
        }
        __syncthreads();
#pragma unroll
        for (int rr = 0; rr < 2; ++rr) {
            float4 h0, h1;
            h0.x = fmaxf(acc[rr*8+0], 0.0f); h0.y = fmaxf(acc[rr*8+1], 0.0f);
            h0.z = fmaxf(acc[rr*8+2], 0.0f); h0.w = fmaxf(acc[rr*8+3], 0.0f);
            h1.x = fmaxf(acc[rr*8+4], 0.0f); h1.y = fmaxf(acc[rr*8+5], 0.0f);
            h1.z = fmaxf(acc[rr*8+6], 0.0f); h1.w = fmaxf(acc[rr*8+7], 0.0f);
            *reinterpret_cast<float4*>(&sh[rp + rr][c4])      = h0;
            *reinterpret_cast<float4*>(&sh[rp + rr][c4 + 32]) = h1;
        }
#pragma unroll
        for (int i = t; i < HID * HID / 4; i += 256)
            reinterpret_cast<float4*>(sW)[i] = reinterpret_cast<const float4*>(W1)[i];
        __syncthreads();

        // layer 1
#pragma unroll
        for (int rr = 0; rr < 2; ++rr)
#pragma unroll
            for (int k = 0; k < 4; ++k) {
                acc[rr * 8 + k]     = sb1[c4 + k];
                acc[rr * 8 + 4 + k] = sb1[c4 + 32 + k];
            }
#pragma unroll
        for (int i = 0; i < HID; ++i) {
            const float4 w0 = *reinterpret_cast<const float4*>(&sW[i * HID + c4]);
            const float4 w1 = *reinterpret_cast<const float4*>(&sW[i * HID + c4 + 32]);
#pragma unroll
            for (int rr = 0; rr < 2; ++rr) {
                const float hb = sh[rp + rr][i];
                acc[rr*8+0] = fmaf(hb, w0.x, acc[rr*8+0]);
                acc[rr*8+1] = fmaf(hb, w0.y, acc[rr*8+1]);
                acc[rr*8+2] = fmaf(hb, w0.z, acc[rr*8+2]);
                acc[rr*8+3] = fmaf(hb, w0.w, acc[rr*8+3]);
                acc[rr*8+4] = fmaf(hb, w1.x, acc[rr*8+4]);
                acc[rr*8+5] = fmaf(hb, w1.y, acc[rr*8+5]);
                acc[rr*8+6] = fmaf(hb, w1.z, acc[rr*8+6]);
                acc[rr*8+7] = fmaf(hb, w1.w, acc[rr*8+7]);
            }
        }
        __syncthreads();
#pragma unroll
        for (int rr = 0; rr < 2; ++rr) {
            float4 h0, h1;
            h0.x = fmaxf(acc[rr*8+0], 0.0f); h0.y = fmaxf(acc[rr*8+1], 0.0f);
            h0.z = fmaxf(acc[rr*8+2], 0.0f); h0.w = fmaxf(acc[rr*8+3], 0.0f);
            h1.x = fmaxf(acc[rr*8+4], 0.0f); h1.y = fmaxf(acc[rr*8+5], 0.0f);
            h1.z = fmaxf(acc[rr*8+6], 0.0f); h1.w = fmaxf(acc[rr*8+7], 0.0f);
            *reinterpret_cast<float4*>(&sh[rp + rr][c4])      = h0;
            *reinterpret_cast<float4*>(&sh[rp + rr][c4 + 32]) = h1;
        }
        __syncthreads();

        // head + sigmoid: 256 threads = 64 rows x 4 units
        {
            const int hr = t >> 2;
            const int jo = t & 3;
            float a2 = sbo[jo];
#pragma unroll
            for (int i = 0; i < HID; ++i) a2 = fmaf(sh[hr][i], sWo[i * 4 + jo], a2);
            float pv = 1.0f / (1.0f + expf(-a2));
            sp[hr][jo] = fminf(fmaxf(pv, EPSF), 1.0f - EPSF);
        }
        __syncthreads();

        if (t < MROWS) {
            const int rr   = growbase + t;
            const float l  = sp[t][0];
            const float gg = sp[t][1];
            const float s  = sp[t][2];
            const float pr = sp[t][3];
            const float il = 1.0f / (1.0f - l);
            g_A1[rr] = (1.0f - s) / (gg * (1.0f - l));
            g_A0[rr] = s / ((1.0f - gg) * (1.0f - l));
            g_B[rr]  = l * il;
            g_o0[rr] = pr / (1.0f - pr);
            g_s1[rr] = 1.0f - s;
            g_gg[rr] = gg;
            __threadfence();
        }
        __syncthreads();
        if (t == 0) {
            __threadfence();
            *reinterpret_cast<volatile int*>(&g_flag[bid]) = 1;
        }
    }

    // ---- wait for this block's constants (producer index = bid >> 3) ----
    {
        const int need = bid >> 3;
        if (t == 0) {
            while (*reinterpret_cast<volatile int*>(&g_flag[need]) == 0) {}
        }
        __syncthreads();
    }

    // =================== scan phase (exact R10 body) ===================
    float (*s_o)[SEGS * OPITCH] = reinterpret_cast<float (*)[SEGS * OPITCH]>(sbuf);

    const float A0 = g_A0[row];
    const float A1 = g_A1[row];
    const float Bc = g_B[row];
    const float s1 = g_s1[row];
    const float gg = g_gg[row];
    const float o0 = g_o0[row];
    const float OMAX = (1.0f - EPSF) / EPSF;

    // compose segment map f(o) = min(a*o + b, c)
    float a = 1.0f, b = 0.0f, cc = OMAX;
#pragma unroll
    for (int j = 0; j < SLEN; ++j) {
        const float A = ((mask >> j) & 1u) ? A1 : A0;
        cc = fminf(fmaf(A, cc, Bc), OMAX);
        b  = fmaf(A, b, Bc);
        a  = A * a;
    }

    // inclusive Kogge-Stone scan over maps
#pragma unroll
    for (int d = 1; d < 32; d <<= 1) {
        const float ap = __shfl_up_sync(0xffffffffu, a,  d);
        const float bp = __shfl_up_sync(0xffffffffu, b,  d);
        const float cq = __shfl_up_sync(0xffffffffu, cc, d);
        if (lane >= d) {
            const float bn = fmaf(a, bp, b);
            const float cn = fminf(fmaf(a, cq, b), cc);
            a  = a * ap;
            b  = bn;
            cc = cn;
        }
    }
    const float ap = __shfl_up_sync(0xffffffffu, a,  1);
    const float bp = __shfl_up_sync(0xffffffffu, b,  1);
    const float cq = __shfl_up_sync(0xffffffffu, cc, 1);
    float o = (lane == 0) ? o0 : fminf(fmaf(ap, o0, bp), cq);

    // emit: batch 4 steps into float4, STS.128
    float* const so = &s_o[w][lane * OPITCH];
#pragma unroll
    for (int j4 = 0; j4 < SLEN / 4; ++j4) {
        float4 ov;
        {   const float A = ((mask >> (4*j4+0)) & 1u) ? A1 : A0;
            ov.x = o;  o = fminf(fmaf(A, o, Bc), OMAX); }
        {   const float A = ((mask >> (4*j4+1)) & 1u) ? A1 : A0;
            ov.y = o;  o = fminf(fmaf(A, o, Bc), OMAX); }
        {   const float A = ((mask >> (4*j4+2)) & 1u) ? A1 : A0;
            ov.z = o;  o = fminf(fmaf(A, o, Bc), OMAX); }
        {   const float A = ((mask >> (4*j4+3)) & 1u) ? A1 : A0;
            ov.w = o;  o = fminf(fmaf(A, o, Bc), OMAX); }
        *reinterpret_cast<float4*>(so + 4 * j4) = ov;
    }
    __syncwarp();

    // drain: LDS.128 + rcp x4 + 2x STG.128 per group
    float* const outc = out + (size_t)row * T_LEN;
    float* const outl = out + (size_t)NUM_B * T_LEN + (size_t)row * T_LEN;
    const int sgl = lane >> 3;
    const int k4  = (lane & 7) * 4;
#pragma unroll
    for (int dd = 0; dd < 8; ++dd) {
        const int seg = dd * 4 + sgl;
        const float4 ov = *reinterpret_cast<const float4*>(&s_o[w][seg * OPITCH + k4]);
        float4 lv, cv;
        float inv;
        asm("rcp.approx.ftz.f32 %0, %1;" : "=f"(inv) : "f"(1.0f + ov.x));
        lv.x = ov.x * inv;  cv.x = fmaf(ov.x, s1, gg) * inv;
        asm("rcp.approx.ftz.f32 %0, %1;" : "=f"(inv) : "f"(1.0f + ov.y));
        lv.y = ov.y * inv;  cv.y = fmaf(ov.y, s1, gg) * inv;
        asm("rcp.approx.ftz.f32 %0, %1;" : "=f"(inv) : "f"(1.0f + ov.z));
        lv.z = ov.z * inv;  cv.z = fmaf(ov.z, s1, gg) * inv;
        asm("rcp.approx.ftz.f32 %0, %1;" : "=f"(inv) : "f"(1.0f + ov.w));
        lv.w = ov.w * inv;  cv.w = fmaf(ov.w, s1, gg) * inv;
        *reinterpret_cast<float4*>(outc + seg * SLEN + k4) = cv;
        *reinterpret_cast<float4*>(outl + seg * SLEN + k4) = lv;
    }
}

// ---------------------------------------------------------------------------
extern "C" void kernel_launch(void* const* d_in, const int* in_sizes, int n_in,
                              void* d_out, int out_size)
{
    const int*   X     = (const int*)  d_in[0];
    const int*   y     = (const int*)  d_in[1];
    const float* embed = (const float*)d_in[2];
    const float* W0    = (const float*)d_in[3];
    const float* b0    = (const float*)d_in[4];
    const float* W1    = (const float*)d_in[5];
    const float* b1    = (const float*)d_in[6];
    const float* Wout  = (const float*)d_in[7];
    const float* bout  = (const float*)d_in[8];

    fused_kernel<<<NUM_B / BWARPS, 256>>>(
        X, y, embed, W0, b0, W1, b1, Wout, bout, (float*)d_out);
}